// round 3
// baseline (speedup 1.0000x reference)
#include <cuda_runtime.h>
#include <cstdint>

#define B_DIM   8
#define N_NODES 100000
#define N_EDGES 3200000

// Node record: 16 floats (64B): slot[2b] = y[b], slot[1] = inv = 1/deg^2
__device__ float g_rec[N_NODES * 16];     // 6.4 MB
__device__ float g_deg[N_NODES];          // 400 KB
__device__ float g_acc[N_NODES * B_DIM];  // 3.2 MB, [N][8]

// ---------------------------------------------------------------------------
// K1: zero deg/acc, build records from y [B,N]
// ---------------------------------------------------------------------------
__global__ void init_kernel(const float* __restrict__ y) {
    int n = blockIdx.x * blockDim.x + threadIdx.x;
    if (n >= N_NODES) return;
    g_deg[n] = 0.0f;
    float4 z = make_float4(0.f, 0.f, 0.f, 0.f);
    float4* acc4 = reinterpret_cast<float4*>(g_acc);
    acc4[2 * n]     = z;
    acc4[2 * n + 1] = z;
    float v0 = y[0 * N_NODES + n];
    float v1 = y[1 * N_NODES + n];
    float v2 = y[2 * N_NODES + n];
    float v3 = y[3 * N_NODES + n];
    float v4 = y[4 * N_NODES + n];
    float v5 = y[5 * N_NODES + n];
    float v6 = y[6 * N_NODES + n];
    float v7 = y[7 * N_NODES + n];
    float4* rec4 = reinterpret_cast<float4*>(g_rec + (size_t)n * 16);
    rec4[0] = make_float4(v0, 0.f, v1, 0.f);   // slot1 = inv, filled later
    rec4[1] = make_float4(v2, 0.f, v3, 0.f);
    rec4[2] = make_float4(v4, 0.f, v5, 0.f);
    rec4[3] = make_float4(v6, 0.f, v7, 0.f);
}

// ---------------------------------------------------------------------------
// K2: deg[n] = segment_sum(attr over ei0)
// ---------------------------------------------------------------------------
__global__ void deg_kernel(const int* __restrict__ edge_index,
                           const float* __restrict__ attr) {
    int e = blockIdx.x * blockDim.x + threadIdx.x;
    if (e >= N_EDGES) return;
    atomicAdd(&g_deg[edge_index[e]], attr[e]);
}

// ---------------------------------------------------------------------------
// K3: rec[n].inv = 1/deg^2
// ---------------------------------------------------------------------------
__global__ void finalize_kernel() {
    int n = blockIdx.x * blockDim.x + threadIdx.x;
    if (n >= N_NODES) return;
    float d = g_deg[n];
    g_rec[(size_t)n * 16 + 1] = 1.0f / (d * d);
}

// ---------------------------------------------------------------------------
// K4: edge pass, 8 lanes per edge (lane = batch element)
// contribution[b] = sqrt(sigmoid(dw)) / deg[n0]^2 * max(y[b,n0]-y[b,n1], 0)
// ---------------------------------------------------------------------------
__global__ void edge_kernel(const int* __restrict__ edge_index,
                            const float* __restrict__ dist_w) {
    unsigned t = blockIdx.x * blockDim.x + threadIdx.x;
    unsigned e = t >> 3;
    int b = t & 7;
    if (e >= N_EDGES) return;

    int n0 = edge_index[e];
    int n1 = edge_index[N_EDGES + e];

    // Lane's own (y[b], aux) from n0's record; lane 0's aux is inv = 1/deg^2
    const float2* r0 = reinterpret_cast<const float2*>(g_rec + (size_t)n0 * 16);
    float2 a = r0[b];
    // y[b] of n1
    float c = g_rec[(size_t)n1 * 16 + 2 * b];

    float s = 0.0f;
    if (b == 0) {
        float dw = dist_w[e];
        // sqrt(sigmoid(dw)) = rsqrt(1 + exp(-dw))
        s = rsqrtf(1.0f + __expf(-dw)) * a.y;
    }
    s = __shfl_sync(0xffffffffu, s, 0, 8);   // broadcast within 8-lane group

    float g = fmaxf(a.x - c, 0.0f) * s;
    if (g != 0.0f) {
        asm volatile("red.global.add.f32 [%0], %1;"
                     :: "l"(g_acc + (size_t)n0 * 8 + b), "f"(g) : "memory");
    }
}

// ---------------------------------------------------------------------------
// K5: out[b,n] = 1 - acc[n,b]
// ---------------------------------------------------------------------------
__global__ void out_kernel(float* __restrict__ out) {
    int n = blockIdx.x * blockDim.x + threadIdx.x;
    if (n >= N_NODES) return;
    const float4* acc4 = reinterpret_cast<const float4*>(g_acc);
    float4 a = acc4[2 * n];
    float4 b = acc4[2 * n + 1];
    out[0 * N_NODES + n] = 1.0f - a.x;
    out[1 * N_NODES + n] = 1.0f - a.y;
    out[2 * N_NODES + n] = 1.0f - a.z;
    out[3 * N_NODES + n] = 1.0f - a.w;
    out[4 * N_NODES + n] = 1.0f - b.x;
    out[5 * N_NODES + n] = 1.0f - b.y;
    out[6 * N_NODES + n] = 1.0f - b.z;
    out[7 * N_NODES + n] = 1.0f - b.w;
}

// ---------------------------------------------------------------------------
extern "C" void kernel_launch(void* const* d_in, const int* in_sizes, int n_in,
                              void* d_out, int out_size) {
    const float* y    = (const float*)d_in[0];
    const float* attr = (const float*)d_in[2];
    const float* dw   = (const float*)d_in[3];
    const int*   ei   = (const int*)d_in[4];
    float* out = (float*)d_out;

    const int TB = 256;
    init_kernel<<<(N_NODES + TB - 1) / TB, TB>>>(y);
    deg_kernel<<<(N_EDGES + TB - 1) / TB, TB>>>(ei, attr);
    finalize_kernel<<<(N_NODES + TB - 1) / TB, TB>>>();
    // 8 threads per edge
    unsigned total = (unsigned)N_EDGES * 8u;
    edge_kernel<<<(total + TB - 1) / TB, TB>>>(ei, dw);
    out_kernel<<<(N_NODES + TB - 1) / TB, TB>>>(out);
}

// round 9
// speedup vs baseline: 1.4513x; 1.4513x over previous
#include <cuda_runtime.h>
#include <cuda_fp16.h>
#include <cstdint>

#define B_DIM   8
#define N_NODES 100000
#define N_EDGES 3200000

// Node record: 8 x uint32 (32B): words 0-3 = y[0..7] as 8 halfs, word 4 = inv (f32 bits)
__device__ unsigned int g_rec[N_NODES * 8];   // 3.2 MB
__device__ float        g_deg[N_NODES];       // 400 KB
__device__ __half       g_acc[N_NODES * 8];   // 1.6 MB, [N][8] half

// Bit-cast helpers (toolkit lacks __half2_as_uint / __uint_as_half2)
__device__ __forceinline__ unsigned int h2u(__half2 h) {
    unsigned int u;
    *reinterpret_cast<__half2*>(&u) = h;
    return u;
}
__device__ __forceinline__ __half2 u2h(unsigned int u) {
    return *reinterpret_cast<__half2*>(&u);
}

// ---------------------------------------------------------------------------
// K1: zero deg/acc, build half records from y [B,N]
// ---------------------------------------------------------------------------
__global__ void init_kernel(const float* __restrict__ y) {
    int n = blockIdx.x * blockDim.x + threadIdx.x;
    if (n >= N_NODES) return;
    g_deg[n] = 0.0f;
    reinterpret_cast<uint4*>(g_acc)[n] = make_uint4(0u, 0u, 0u, 0u);

    float v0 = y[0 * N_NODES + n];
    float v1 = y[1 * N_NODES + n];
    float v2 = y[2 * N_NODES + n];
    float v3 = y[3 * N_NODES + n];
    float v4 = y[4 * N_NODES + n];
    float v5 = y[5 * N_NODES + n];
    float v6 = y[6 * N_NODES + n];
    float v7 = y[7 * N_NODES + n];
    __half2 p0 = __floats2half2_rn(v0, v1);
    __half2 p1 = __floats2half2_rn(v2, v3);
    __half2 p2 = __floats2half2_rn(v4, v5);
    __half2 p3 = __floats2half2_rn(v6, v7);
    uint4* rec = reinterpret_cast<uint4*>(g_rec);
    rec[2 * n]     = make_uint4(h2u(p0), h2u(p1), h2u(p2), h2u(p3));
    rec[2 * n + 1] = make_uint4(0u, 0u, 0u, 0u);  // word 0 = inv, filled later
}

// ---------------------------------------------------------------------------
// K2: deg[n] = segment_sum(attr over ei0)
// ---------------------------------------------------------------------------
__global__ void deg_kernel(const int* __restrict__ edge_index,
                           const float* __restrict__ attr) {
    int e = blockIdx.x * blockDim.x + threadIdx.x;
    if (e >= N_EDGES) return;
    atomicAdd(&g_deg[edge_index[e]], attr[e]);
}

// ---------------------------------------------------------------------------
// K3: rec[n].inv = 1/deg^2
// ---------------------------------------------------------------------------
__global__ void finalize_kernel() {
    int n = blockIdx.x * blockDim.x + threadIdx.x;
    if (n >= N_NODES) return;
    float d = g_deg[n];
    reinterpret_cast<float*>(g_rec)[8 * n + 4] = 1.0f / (d * d);
}

// ---------------------------------------------------------------------------
// K4: one thread per edge; half2 math; single v4.f16x2 reduction
// contribution[b] = sqrt(sigmoid(dw)) / deg[n0]^2 * max(y[b,n0]-y[b,n1], 0)
// ---------------------------------------------------------------------------
__global__ void edge_kernel(const int* __restrict__ edge_index,
                            const float* __restrict__ dist_w) {
    int e = blockIdx.x * blockDim.x + threadIdx.x;
    if (e >= N_EDGES) return;

    int n0 = edge_index[e];
    int n1 = edge_index[N_EDGES + e];

    const uint4* rec = reinterpret_cast<const uint4*>(g_rec);
    uint4 A  = rec[2 * n0];                                  // y[n0], 8 halfs
    uint4 Bv = rec[2 * n1];                                  // y[n1], 8 halfs
    float inv = reinterpret_cast<const float*>(g_rec)[8 * n0 + 4];  // same 32B sector pair as A -> L1 hit

    // s = sqrt(sigmoid(dw)) * inv ;  sqrt(sigmoid(x)) = rsqrt(1+exp(-x))
    float s = rsqrtf(1.0f + __expf(-dist_w[e])) * inv;
    __half2 s2 = __float2half2_rn(s);
    __half2 z  = __float2half2_rn(0.0f);

    __half2 g0 = __hmul2(__hmax2(__hsub2(u2h(A.x), u2h(Bv.x)), z), s2);
    __half2 g1 = __hmul2(__hmax2(__hsub2(u2h(A.y), u2h(Bv.y)), z), s2);
    __half2 g2 = __hmul2(__hmax2(__hsub2(u2h(A.z), u2h(Bv.z)), z), s2);
    __half2 g3 = __hmul2(__hmax2(__hsub2(u2h(A.w), u2h(Bv.w)), z), s2);

    unsigned int u0 = h2u(g0);
    unsigned int u1 = h2u(g1);
    unsigned int u2 = h2u(g2);
    unsigned int u3 = h2u(g3);

    if (u0 | u1 | u2 | u3) {
        asm volatile("red.global.add.noftz.v4.f16x2 [%0], {%1, %2, %3, %4};"
                     :: "l"(g_acc + (size_t)n0 * 8),
                        "r"(u0), "r"(u1), "r"(u2), "r"(u3)
                     : "memory");
    }
}

// ---------------------------------------------------------------------------
// K5: out[b,n] = 1 - acc[n,b]
// ---------------------------------------------------------------------------
__global__ void out_kernel(float* __restrict__ out) {
    int n = blockIdx.x * blockDim.x + threadIdx.x;
    if (n >= N_NODES) return;
    uint4 a = reinterpret_cast<const uint4*>(g_acc)[n];
    float2 f0 = __half22float2(u2h(a.x));
    float2 f1 = __half22float2(u2h(a.y));
    float2 f2 = __half22float2(u2h(a.z));
    float2 f3 = __half22float2(u2h(a.w));
    out[0 * N_NODES + n] = 1.0f - f0.x;
    out[1 * N_NODES + n] = 1.0f - f0.y;
    out[2 * N_NODES + n] = 1.0f - f1.x;
    out[3 * N_NODES + n] = 1.0f - f1.y;
    out[4 * N_NODES + n] = 1.0f - f2.x;
    out[5 * N_NODES + n] = 1.0f - f2.y;
    out[6 * N_NODES + n] = 1.0f - f3.x;
    out[7 * N_NODES + n] = 1.0f - f3.y;
}

// ---------------------------------------------------------------------------
extern "C" void kernel_launch(void* const* d_in, const int* in_sizes, int n_in,
                              void* d_out, int out_size) {
    const float* y    = (const float*)d_in[0];
    const float* attr = (const float*)d_in[2];
    const float* dw   = (const float*)d_in[3];
    const int*   ei   = (const int*)d_in[4];
    float* out = (float*)d_out;

    const int TB = 256;
    init_kernel<<<(N_NODES + TB - 1) / TB, TB>>>(y);
    deg_kernel<<<(N_EDGES + TB - 1) / TB, TB>>>(ei, attr);
    finalize_kernel<<<(N_NODES + TB - 1) / TB, TB>>>();
    edge_kernel<<<(N_EDGES + TB - 1) / TB, TB>>>(ei, dw);
    out_kernel<<<(N_NODES + TB - 1) / TB, TB>>>(out);
}

// round 10
// speedup vs baseline: 1.4956x; 1.0305x over previous
#include <cuda_runtime.h>
#include <cuda_fp16.h>
#include <cstdint>

#define B_DIM   8
#define N_NODES 100000
#define N_EDGES 3200000

// Node record: 8 x uint32 (32B, 32B-aligned):
//   words 0-3 = y[0..7] as 8 halfs, word 4 = inv = 1/deg^2 (f32 bits), words 5-7 pad
__device__ __align__(32) unsigned int g_rec[N_NODES * 8];   // 3.2 MB
__device__ float  g_deg[N_NODES];                           // 400 KB
__device__ __half g_acc[N_NODES * 8];                       // 1.6 MB, [N][8] half

// Bit-cast helpers
__device__ __forceinline__ unsigned int h2u(__half2 h) {
    unsigned int u;
    *reinterpret_cast<__half2*>(&u) = h;
    return u;
}
__device__ __forceinline__ __half2 u2h(unsigned int u) {
    return *reinterpret_cast<__half2*>(&u);
}

// ---------------------------------------------------------------------------
// K1: zero deg/acc, build half records from y [B,N]
// ---------------------------------------------------------------------------
__global__ void init_kernel(const float* __restrict__ y) {
    int n = blockIdx.x * blockDim.x + threadIdx.x;
    if (n >= N_NODES) return;
    g_deg[n] = 0.0f;
    reinterpret_cast<uint4*>(g_acc)[n] = make_uint4(0u, 0u, 0u, 0u);

    float v0 = y[0 * N_NODES + n];
    float v1 = y[1 * N_NODES + n];
    float v2 = y[2 * N_NODES + n];
    float v3 = y[3 * N_NODES + n];
    float v4 = y[4 * N_NODES + n];
    float v5 = y[5 * N_NODES + n];
    float v6 = y[6 * N_NODES + n];
    float v7 = y[7 * N_NODES + n];
    __half2 p0 = __floats2half2_rn(v0, v1);
    __half2 p1 = __floats2half2_rn(v2, v3);
    __half2 p2 = __floats2half2_rn(v4, v5);
    __half2 p3 = __floats2half2_rn(v6, v7);
    uint4* rec = reinterpret_cast<uint4*>(g_rec);
    rec[2 * n]     = make_uint4(h2u(p0), h2u(p1), h2u(p2), h2u(p3));
    rec[2 * n + 1] = make_uint4(0u, 0u, 0u, 0u);  // word 0 = inv, filled later
}

// ---------------------------------------------------------------------------
// K2: deg[n] = segment_sum(attr over ei0)
// ---------------------------------------------------------------------------
__global__ void deg_kernel(const int* __restrict__ edge_index,
                           const float* __restrict__ attr) {
    int e = blockIdx.x * blockDim.x + threadIdx.x;
    if (e >= N_EDGES) return;
    atomicAdd(&g_deg[edge_index[e]], attr[e]);
}

// ---------------------------------------------------------------------------
// K3: rec[n].inv = 1/deg^2
// ---------------------------------------------------------------------------
__global__ void finalize_kernel() {
    int n = blockIdx.x * blockDim.x + threadIdx.x;
    if (n >= N_NODES) return;
    float d = g_deg[n];
    reinterpret_cast<float*>(g_rec)[8 * n + 4] = 1.0f / (d * d);
}

// ---------------------------------------------------------------------------
// K4: one thread per edge; 256-bit record load (y + inv in ONE instruction);
// half2 math; single v4.f16x2 reduction.
// contribution[b] = sqrt(sigmoid(dw)) / deg[n0]^2 * max(y[b,n0]-y[b,n1], 0)
// ---------------------------------------------------------------------------
__global__ void edge_kernel(const int* __restrict__ edge_index,
                            const float* __restrict__ dist_w) {
    int e = blockIdx.x * blockDim.x + threadIdx.x;
    if (e >= N_EDGES) return;

    int n0 = edge_index[e];
    int n1 = edge_index[N_EDGES + e];

    // 256-bit load of n0's full record: r0-r3 = y halfs, r4 = inv bits
    unsigned int r0, r1, r2, r3, r4, r5, r6, r7;
    asm volatile("ld.global.nc.v8.b32 {%0,%1,%2,%3,%4,%5,%6,%7}, [%8];"
                 : "=r"(r0), "=r"(r1), "=r"(r2), "=r"(r3),
                   "=r"(r4), "=r"(r5), "=r"(r6), "=r"(r7)
                 : "l"(g_rec + (size_t)n0 * 8));

    const uint4* rec = reinterpret_cast<const uint4*>(g_rec);
    uint4 Bv = rec[2 * n1];                                  // y[n1], 8 halfs
    float inv = __uint_as_float(r4);

    // s = sqrt(sigmoid(dw)) * inv ;  sqrt(sigmoid(x)) = rsqrt(1+exp(-x))
    float s = rsqrtf(1.0f + __expf(-dist_w[e])) * inv;
    __half2 s2 = __float2half2_rn(s);
    __half2 z  = __float2half2_rn(0.0f);

    __half2 g0 = __hmul2(__hmax2(__hsub2(u2h(r0), u2h(Bv.x)), z), s2);
    __half2 g1 = __hmul2(__hmax2(__hsub2(u2h(r1), u2h(Bv.y)), z), s2);
    __half2 g2 = __hmul2(__hmax2(__hsub2(u2h(r2), u2h(Bv.z)), z), s2);
    __half2 g3 = __hmul2(__hmax2(__hsub2(u2h(r3), u2h(Bv.w)), z), s2);

    unsigned int u0 = h2u(g0);
    unsigned int u1 = h2u(g1);
    unsigned int u2 = h2u(g2);
    unsigned int u3 = h2u(g3);

    if (u0 | u1 | u2 | u3) {
        asm volatile("red.global.add.noftz.v4.f16x2 [%0], {%1, %2, %3, %4};"
                     :: "l"(g_acc + (size_t)n0 * 8),
                        "r"(u0), "r"(u1), "r"(u2), "r"(u3)
                     : "memory");
    }
}

// ---------------------------------------------------------------------------
// K5: out[b,n] = 1 - acc[n,b]
// ---------------------------------------------------------------------------
__global__ void out_kernel(float* __restrict__ out) {
    int n = blockIdx.x * blockDim.x + threadIdx.x;
    if (n >= N_NODES) return;
    uint4 a = reinterpret_cast<const uint4*>(g_acc)[n];
    float2 f0 = __half22float2(u2h(a.x));
    float2 f1 = __half22float2(u2h(a.y));
    float2 f2 = __half22float2(u2h(a.z));
    float2 f3 = __half22float2(u2h(a.w));
    out[0 * N_NODES + n] = 1.0f - f0.x;
    out[1 * N_NODES + n] = 1.0f - f0.y;
    out[2 * N_NODES + n] = 1.0f - f1.x;
    out[3 * N_NODES + n] = 1.0f - f1.y;
    out[4 * N_NODES + n] = 1.0f - f2.x;
    out[5 * N_NODES + n] = 1.0f - f2.y;
    out[6 * N_NODES + n] = 1.0f - f3.x;
    out[7 * N_NODES + n] = 1.0f - f3.y;
}

// ---------------------------------------------------------------------------
extern "C" void kernel_launch(void* const* d_in, const int* in_sizes, int n_in,
                              void* d_out, int out_size) {
    const float* y    = (const float*)d_in[0];
    const float* attr = (const float*)d_in[2];
    const float* dw   = (const float*)d_in[3];
    const int*   ei   = (const int*)d_in[4];
    float* out = (float*)d_out;

    const int TB = 256;
    init_kernel<<<(N_NODES + TB - 1) / TB, TB>>>(y);
    deg_kernel<<<(N_EDGES + TB - 1) / TB, TB>>>(ei, attr);
    finalize_kernel<<<(N_NODES + TB - 1) / TB, TB>>>();
    edge_kernel<<<(N_EDGES + TB - 1) / TB, TB>>>(ei, dw);
    out_kernel<<<(N_NODES + TB - 1) / TB, TB>>>(out);
}

// round 11
// speedup vs baseline: 1.5435x; 1.0320x over previous
#include <cuda_runtime.h>
#include <cuda_fp16.h>
#include <cstdint>

#define B_DIM   8
#define N_NODES 100000
#define N_EDGES 3200000

// Node record: 16 B = y[0..7] as 8 halfs (uint4)
__device__ __align__(16) unsigned int g_rec[N_NODES * 4];   // 1.6 MB
__device__ float  g_deg[N_NODES];                           // 400 KB
__device__ __half g_acc[N_NODES * 8];                       // 1.6 MB, [N][8] half

// Bit-cast helpers
__device__ __forceinline__ unsigned int h2u(__half2 h) {
    unsigned int u;
    *reinterpret_cast<__half2*>(&u) = h;
    return u;
}
__device__ __forceinline__ __half2 u2h(unsigned int u) {
    return *reinterpret_cast<__half2*>(&u);
}

// ---------------------------------------------------------------------------
// K1: zero deg/acc, build half records from y [B,N]
// ---------------------------------------------------------------------------
__global__ void init_kernel(const float* __restrict__ y) {
    int n = blockIdx.x * blockDim.x + threadIdx.x;
    if (n >= N_NODES) return;
    g_deg[n] = 0.0f;
    reinterpret_cast<uint4*>(g_acc)[n] = make_uint4(0u, 0u, 0u, 0u);

    float v0 = y[0 * N_NODES + n];
    float v1 = y[1 * N_NODES + n];
    float v2 = y[2 * N_NODES + n];
    float v3 = y[3 * N_NODES + n];
    float v4 = y[4 * N_NODES + n];
    float v5 = y[5 * N_NODES + n];
    float v6 = y[6 * N_NODES + n];
    float v7 = y[7 * N_NODES + n];
    __half2 p0 = __floats2half2_rn(v0, v1);
    __half2 p1 = __floats2half2_rn(v2, v3);
    __half2 p2 = __floats2half2_rn(v4, v5);
    __half2 p3 = __floats2half2_rn(v6, v7);
    reinterpret_cast<uint4*>(g_rec)[n] =
        make_uint4(h2u(p0), h2u(p1), h2u(p2), h2u(p3));
}

// ---------------------------------------------------------------------------
// K2: deg[n] = segment_sum(attr over ei0)
// ---------------------------------------------------------------------------
__global__ void deg_kernel(const int* __restrict__ edge_index,
                           const float* __restrict__ attr) {
    int e = blockIdx.x * blockDim.x + threadIdx.x;
    if (e >= N_EDGES) return;
    atomicAdd(&g_deg[edge_index[e]], attr[e]);
}

// ---------------------------------------------------------------------------
// K3: edge pass; accumulates RAW weighted diffs (inv factored out to K4):
//   acc[n0][b] += sqrt(sigmoid(dw)) * max(y[b,n0]-y[b,n1], 0)
// 3 scattered line-touches per edge: A gather, B gather, red.
// ---------------------------------------------------------------------------
__global__ void edge_kernel(const int* __restrict__ edge_index,
                            const float* __restrict__ dist_w) {
    int e = blockIdx.x * blockDim.x + threadIdx.x;
    if (e >= N_EDGES) return;

    int n0 = edge_index[e];
    int n1 = edge_index[N_EDGES + e];

    const uint4* rec = reinterpret_cast<const uint4*>(g_rec);
    uint4 A  = rec[n0];
    uint4 Bv = rec[n1];

    // w = sqrt(sigmoid(dw)) = rsqrt(1 + exp(-dw))
    float w = rsqrtf(1.0f + __expf(-dist_w[e]));
    __half2 s2 = __float2half2_rn(w);
    __half2 z  = __float2half2_rn(0.0f);

    __half2 g0 = __hmul2(__hmax2(__hsub2(u2h(A.x), u2h(Bv.x)), z), s2);
    __half2 g1 = __hmul2(__hmax2(__hsub2(u2h(A.y), u2h(Bv.y)), z), s2);
    __half2 g2 = __hmul2(__hmax2(__hsub2(u2h(A.z), u2h(Bv.z)), z), s2);
    __half2 g3 = __hmul2(__hmax2(__hsub2(u2h(A.w), u2h(Bv.w)), z), s2);

    unsigned int u0 = h2u(g0);
    unsigned int u1 = h2u(g1);
    unsigned int u2 = h2u(g2);
    unsigned int u3 = h2u(g3);

    if (u0 | u1 | u2 | u3) {
        asm volatile("red.global.add.noftz.v4.f16x2 [%0], {%1, %2, %3, %4};"
                     :: "l"(g_acc + (size_t)n0 * 8),
                        "r"(u0), "r"(u1), "r"(u2), "r"(u3)
                     : "memory");
    }
}

// ---------------------------------------------------------------------------
// K4: out[b,n] = 1 - acc[n,b] / deg[n]^2   (inv applied once per node)
// ---------------------------------------------------------------------------
__global__ void out_kernel(float* __restrict__ out) {
    int n = blockIdx.x * blockDim.x + threadIdx.x;
    if (n >= N_NODES) return;
    float d = g_deg[n];
    float inv = 1.0f / (d * d);
    uint4 a = reinterpret_cast<const uint4*>(g_acc)[n];
    float2 f0 = __half22float2(u2h(a.x));
    float2 f1 = __half22float2(u2h(a.y));
    float2 f2 = __half22float2(u2h(a.z));
    float2 f3 = __half22float2(u2h(a.w));
    out[0 * N_NODES + n] = 1.0f - inv * f0.x;
    out[1 * N_NODES + n] = 1.0f - inv * f0.y;
    out[2 * N_NODES + n] = 1.0f - inv * f1.x;
    out[3 * N_NODES + n] = 1.0f - inv * f1.y;
    out[4 * N_NODES + n] = 1.0f - inv * f2.x;
    out[5 * N_NODES + n] = 1.0f - inv * f2.y;
    out[6 * N_NODES + n] = 1.0f - inv * f3.x;
    out[7 * N_NODES + n] = 1.0f - inv * f3.y;
}

// ---------------------------------------------------------------------------
extern "C" void kernel_launch(void* const* d_in, const int* in_sizes, int n_in,
                              void* d_out, int out_size) {
    const float* y    = (const float*)d_in[0];
    const float* attr = (const float*)d_in[2];
    const float* dw   = (const float*)d_in[3];
    const int*   ei   = (const int*)d_in[4];
    float* out = (float*)d_out;

    const int TB = 256;
    init_kernel<<<(N_NODES + TB - 1) / TB, TB>>>(y);
    deg_kernel<<<(N_EDGES + TB - 1) / TB, TB>>>(ei, attr);
    edge_kernel<<<(N_EDGES + TB - 1) / TB, TB>>>(ei, dw);
    out_kernel<<<(N_NODES + TB - 1) / TB, TB>>>(out);
}

// round 12
// speedup vs baseline: 1.7008x; 1.1019x over previous
#include <cuda_runtime.h>
#include <cuda_fp16.h>
#include <cstdint>

#define B_DIM   8
#define N_NODES 100000
#define N_EDGES 3200000
#define E_HALF  (N_EDGES / 2)

// Node record: 16 B = y[0..7] as 8 halfs (uint4)
__device__ __align__(16) unsigned int g_rec[N_NODES * 4];   // 1.6 MB
__device__ float  g_deg[N_NODES];                           // 400 KB
__device__ __half g_acc[N_NODES * 8];                       // 1.6 MB, [N][8] half

// Bit-cast helpers
__device__ __forceinline__ unsigned int h2u(__half2 h) {
    unsigned int u;
    *reinterpret_cast<__half2*>(&u) = h;
    return u;
}
__device__ __forceinline__ __half2 u2h(unsigned int u) {
    return *reinterpret_cast<__half2*>(&u);
}

// ---------------------------------------------------------------------------
// K1: zero deg/acc, build half records from y [B,N]
// ---------------------------------------------------------------------------
__global__ void init_kernel(const float* __restrict__ y) {
    int n = blockIdx.x * blockDim.x + threadIdx.x;
    if (n >= N_NODES) return;
    g_deg[n] = 0.0f;
    reinterpret_cast<uint4*>(g_acc)[n] = make_uint4(0u, 0u, 0u, 0u);

    float v0 = y[0 * N_NODES + n];
    float v1 = y[1 * N_NODES + n];
    float v2 = y[2 * N_NODES + n];
    float v3 = y[3 * N_NODES + n];
    float v4 = y[4 * N_NODES + n];
    float v5 = y[5 * N_NODES + n];
    float v6 = y[6 * N_NODES + n];
    float v7 = y[7 * N_NODES + n];
    __half2 p0 = __floats2half2_rn(v0, v1);
    __half2 p1 = __floats2half2_rn(v2, v3);
    __half2 p2 = __floats2half2_rn(v4, v5);
    __half2 p3 = __floats2half2_rn(v6, v7);
    reinterpret_cast<uint4*>(g_rec)[n] =
        make_uint4(h2u(p0), h2u(p1), h2u(p2), h2u(p3));
}

// ---------------------------------------------------------------------------
// K2 (fused): per edge, BOTH
//   deg[n0] += attr[e]                                  (f32 RED)
//   acc[n0][b] += sqrt(sigmoid(dw[e])) * max(y[b,n0]-y[b,n1], 0)  (f16x2 v4 RED)
// Two edges per thread (e and e+E/2) for doubled MLP.
// ---------------------------------------------------------------------------
__device__ __forceinline__ void edge_body(int n0, uint4 A, uint4 Bv, float w) {
    __half2 s2 = __float2half2_rn(w);
    __half2 z  = __float2half2_rn(0.0f);
    unsigned int u0 = h2u(__hmul2(__hmax2(__hsub2(u2h(A.x), u2h(Bv.x)), z), s2));
    unsigned int u1 = h2u(__hmul2(__hmax2(__hsub2(u2h(A.y), u2h(Bv.y)), z), s2));
    unsigned int u2 = h2u(__hmul2(__hmax2(__hsub2(u2h(A.z), u2h(Bv.z)), z), s2));
    unsigned int u3 = h2u(__hmul2(__hmax2(__hsub2(u2h(A.w), u2h(Bv.w)), z), s2));
    if (u0 | u1 | u2 | u3) {
        asm volatile("red.global.add.noftz.v4.f16x2 [%0], {%1, %2, %3, %4};"
                     :: "l"(g_acc + (size_t)n0 * 8),
                        "r"(u0), "r"(u1), "r"(u2), "r"(u3)
                     : "memory");
    }
}

__global__ void fused_kernel(const int* __restrict__ edge_index,
                             const float* __restrict__ attr,
                             const float* __restrict__ dist_w) {
    int t = blockIdx.x * blockDim.x + threadIdx.x;
    if (t >= E_HALF) return;
    int eA = t;
    int eB = t + E_HALF;

    // Coalesced index / weight streams for both edges
    int a0 = edge_index[eA];
    int a1 = edge_index[N_EDGES + eA];
    int b0 = edge_index[eB];
    int b1 = edge_index[N_EDGES + eB];

    const uint4* rec = reinterpret_cast<const uint4*>(g_rec);
    // Issue all four scattered gathers up front (MLP)
    uint4 Aa = rec[a0];
    uint4 Ab = rec[a1];
    uint4 Ba = rec[b0];
    uint4 Bb = rec[b1];

    float atA = attr[eA];
    float atB = attr[eB];
    float wA  = rsqrtf(1.0f + __expf(-dist_w[eA]));
    float wB  = rsqrtf(1.0f + __expf(-dist_w[eB]));

    // deg accumulation (scattered f32 RED, no return)
    atomicAdd(&g_deg[a0], atA);
    atomicAdd(&g_deg[b0], atB);

    edge_body(a0, Aa, Ab, wA);
    edge_body(b0, Ba, Bb, wB);
}

// ---------------------------------------------------------------------------
// K3: out[b,n] = 1 - acc[n,b] / deg[n]^2   (inv applied once per node)
// ---------------------------------------------------------------------------
__global__ void out_kernel(float* __restrict__ out) {
    int n = blockIdx.x * blockDim.x + threadIdx.x;
    if (n >= N_NODES) return;
    float d = g_deg[n];
    float inv = 1.0f / (d * d);
    uint4 a = reinterpret_cast<const uint4*>(g_acc)[n];
    float2 f0 = __half22float2(u2h(a.x));
    float2 f1 = __half22float2(u2h(a.y));
    float2 f2 = __half22float2(u2h(a.z));
    float2 f3 = __half22float2(u2h(a.w));
    out[0 * N_NODES + n] = 1.0f - inv * f0.x;
    out[1 * N_NODES + n] = 1.0f - inv * f0.y;
    out[2 * N_NODES + n] = 1.0f - inv * f1.x;
    out[3 * N_NODES + n] = 1.0f - inv * f1.y;
    out[4 * N_NODES + n] = 1.0f - inv * f2.x;
    out[5 * N_NODES + n] = 1.0f - inv * f2.y;
    out[6 * N_NODES + n] = 1.0f - inv * f3.x;
    out[7 * N_NODES + n] = 1.0f - inv * f3.y;
}

// ---------------------------------------------------------------------------
extern "C" void kernel_launch(void* const* d_in, const int* in_sizes, int n_in,
                              void* d_out, int out_size) {
    const float* y    = (const float*)d_in[0];
    const float* attr = (const float*)d_in[2];
    const float* dw   = (const float*)d_in[3];
    const int*   ei   = (const int*)d_in[4];
    float* out = (float*)d_out;

    const int TB = 256;
    init_kernel<<<(N_NODES + TB - 1) / TB, TB>>>(y);
    fused_kernel<<<(E_HALF + TB - 1) / TB, TB>>>(ei, attr, dw);
    out_kernel<<<(N_NODES + TB - 1) / TB, TB>>>(out);
}